// round 11
// baseline (speedup 1.0000x reference)
#include <cuda_runtime.h>
#include <math.h>

// ViT fused R11: smem-wavefront diet.
//  - softmax fused into A1/A2 via shfl reductions (kills 16-way-conflict loops)
//  - L1 pass A merges Q+K weight rows per lane (tok LDS halved)
//  - parity-interleaved sample halves (bank-disjoint: odd*784 = +16 banks)
//  - QB/KB strides 144/80, KB2 +8 pad, fc1w stride 204, G2 j-parity split

#define GRP  16
#define NTHR 256

static constexpr int SM_PB  = 0;        // 16*784 = 12544
static constexpr int SM_PE  = 12544;    // 784
static constexpr int SM_QB  = 13328;    // 2304 (16 samples x stride 144) ; fc1w staging 16x204=3264 spans QB+KB
static constexpr int SM_KB  = 15632;    // 2304
static constexpr int SM_F2W = 17936;    // 160
static constexpr int SM_F1B = 18096;    // 16
static constexpr int SM_F2B = 18112;    // 16
static constexpr int SM_H   = 18128;    // 256
static constexpr int SM_LG  = 18384;    // 256
static constexpr int SM_TOT = 18640;    // 74560 bytes -> 3 CTAs/SM

__device__ __forceinline__ float dot4(float4 w, float4 a, float acc) {
    acc = fmaf(w.x, a.x, acc); acc = fmaf(w.y, a.y, acc);
    acc = fmaf(w.z, a.z, acc); return fmaf(w.w, a.w, acc);
}

__global__ __launch_bounds__(NTHR, 3)
void vit_fused_kernel(
    const float* __restrict__ x, const float* __restrict__ pos_emb,
    const float* __restrict__ WQ1, const float* __restrict__ WK1, const float* __restrict__ WV1,
    const float* __restrict__ WQ2, const float* __restrict__ WK2, const float* __restrict__ WV2,
    const float* __restrict__ fc1w, const float* __restrict__ fc1b,
    const float* __restrict__ fc2w, const float* __restrict__ fc2b,
    float* __restrict__ out, int B)
{
    extern __shared__ float sh[];
    const int tid  = threadIdx.x;
    const int lane = tid & 31;
    const int wrp  = tid >> 5;          // 0..7 : patch slot in P-phases
    const int t    = tid & 15;          // dim within sample
    const int ls   = tid >> 4;          // sample slot
    const int b0   = blockIdx.x * GRP;
    const int b    = b0 + ls;
    const float INV7 = 0.14285714285714285f;
    float* myrow = &sh[SM_PB + ls * 784];

    // ---------------- phase 0: patchify + constants ----------------
    for (int idx = tid; idx < GRP * 784; idx += NTHR) {
        int lsi = idx / 784, pix = idx - lsi * 784;
        int bb = b0 + lsi;
        float g = 0.f;
        if (bb < B) {
            const float* xp = x + (size_t)bb * 2352 + pix;
            g = 0.299f * xp[0] + 0.587f * xp[784] + 0.114f * xp[1568];
        }
        int y = pix / 28, xx = pix - y * 28;
        sh[SM_PB + lsi * 784 + ((y >> 2) * 7 + (xx >> 2)) * 16 + (y & 3) * 4 + (xx & 3)] = g;
    }
    for (int idx = tid; idx < 784; idx += NTHR) sh[SM_PE + idx] = pos_emb[idx];
    if (tid < 160) sh[SM_F2W + tid] = fc2w[tid];
    if (tid < 16)  sh[SM_F1B + tid] = fc1b[tid];
    if (tid < 10)  sh[SM_F2B + tid] = fc2b[tid];

    // ---------------- layer 1: chunks of 8 patches ----------------
    float S1[16];
#pragma unroll
    for (int e = 0; e < 16; e++) S1[e] = 0.f;

#pragma unroll 1
    for (int c0 = 0; c0 < 49; c0 += 8) {
        const int np = min(8, 49 - c0);
        __syncthreads();
        float vacc[8];
        const int s   = c0 + wrp;
        const int row = lane & 15;
        const int par = lane >> 4;          // sample parity
        if (wrp < np) {
            const float4* pe4 = reinterpret_cast<const float4*>(&sh[SM_PE + s * 16]);
            float4 p0 = pe4[0], p1 = pe4[1], p2 = pe4[2], p3 = pe4[3];
            // ---- pass A: merged Q+K rows per lane; 8 samples (parity-interleaved) ----
            {
                const float4* Wq = reinterpret_cast<const float4*>(WQ1 + s * 512 + row * 32);
                const float4* Wk = reinterpret_cast<const float4*>(WK1 + s * 512 + row * 32);
                float4 q0 = Wq[0], q1 = Wq[1], q2 = Wq[2], q3 = Wq[3];
                float4 k0 = Wk[0], k1 = Wk[1], k2 = Wk[2], k3 = Wk[3];
                float peq = dot4(Wq[7], p3, dot4(Wq[6], p2, dot4(Wq[5], p1, dot4(Wq[4], p0, 0.f))));
                float pek = dot4(Wk[7], p3, dot4(Wk[6], p2, dot4(Wk[5], p1, dot4(Wk[4], p0, 0.f))));
#pragma unroll 2
                for (int ii = 0; ii < 8; ii++) {
                    const int i = 2 * ii + par;
                    const float4* tk = reinterpret_cast<const float4*>(&sh[SM_PB + i * 784 + s * 16]);
                    float4 a0 = tk[0], a1 = tk[1], a2 = tk[2], a3 = tk[3];
                    float q = dot4(q3, a3, dot4(q2, a2, dot4(q1, a1, dot4(q0, a0, peq))));
                    float k = dot4(k3, a3, dot4(k2, a2, dot4(k1, a1, dot4(k0, a0, pek))));
                    sh[SM_QB + i * 144 + wrp * 16 + row] = q * INV7;
                    sh[SM_KB + i * 144 + wrp * 16 + row] = k;
                }
            }
            // ---- pass B: V rows (deferred writes) ----
            {
                const float4* Wv = reinterpret_cast<const float4*>(WV1 + s * 512 + row * 32);
                float4 v0 = Wv[0], v1 = Wv[1], v2 = Wv[2], v3 = Wv[3];
                float pev = dot4(Wv[7], p3, dot4(Wv[6], p2, dot4(Wv[5], p1, dot4(Wv[4], p0, 0.f))));
#pragma unroll 2
                for (int ii = 0; ii < 8; ii++) {
                    const int i = 2 * ii + par;
                    const float4* tk = reinterpret_cast<const float4*>(&sh[SM_PB + i * 784 + s * 16]);
                    vacc[ii] = dot4(v3, tk[3], dot4(v2, tk[2], dot4(v1, tk[1], dot4(v0, tk[0], pev))));
                }
            }
        }
        __syncwarp();   // all patch-row reads complete before V overwrites
        if (wrp < np) {
#pragma unroll
            for (int ii = 0; ii < 8; ii++)
                sh[SM_PB + (2 * ii + par) * 784 + s * 16 + row] = vacc[ii];
        }
        __syncthreads();
        // ---- G-phase: warp = 2 samples ----
#pragma unroll 1
        for (int j = 0; j < np; j++) {
            float q = sh[SM_QB + ls * 144 + j * 16 + t];
            const float4* kr = reinterpret_cast<const float4*>(&sh[SM_KB + ls * 144 + j * 16]);
            float4 k0 = kr[0], k1 = kr[1], k2 = kr[2], k3 = kr[3];
            S1[0]  = fmaf(q, k0.x, S1[0]);  S1[1]  = fmaf(q, k0.y, S1[1]);
            S1[2]  = fmaf(q, k0.z, S1[2]);  S1[3]  = fmaf(q, k0.w, S1[3]);
            S1[4]  = fmaf(q, k1.x, S1[4]);  S1[5]  = fmaf(q, k1.y, S1[5]);
            S1[6]  = fmaf(q, k1.z, S1[6]);  S1[7]  = fmaf(q, k1.w, S1[7]);
            S1[8]  = fmaf(q, k2.x, S1[8]);  S1[9]  = fmaf(q, k2.y, S1[9]);
            S1[10] = fmaf(q, k2.z, S1[10]); S1[11] = fmaf(q, k2.w, S1[11]);
            S1[12] = fmaf(q, k3.x, S1[12]); S1[13] = fmaf(q, k3.y, S1[13]);
            S1[14] = fmaf(q, k3.z, S1[14]); S1[15] = fmaf(q, k3.w, S1[15]);
        }
    }

    // ---------------- A1 + softmax1 fused (in place) ----------------
#pragma unroll 1
    for (int sb = 0; sb < 49; sb += 7) {
        float a[7];
#pragma unroll
        for (int u = 0; u < 7; u++) {
            const float4* vr = reinterpret_cast<const float4*>(&myrow[(sb + u) * 16]);
            float4 v0 = vr[0], v1 = vr[1], v2 = vr[2], v3 = vr[3];
            float a0 = 0.f, a1 = 0.f;
            a0 = fmaf(S1[0],  v0.x, a0); a1 = fmaf(S1[1],  v0.y, a1);
            a0 = fmaf(S1[2],  v0.z, a0); a1 = fmaf(S1[3],  v0.w, a1);
            a0 = fmaf(S1[4],  v1.x, a0); a1 = fmaf(S1[5],  v1.y, a1);
            a0 = fmaf(S1[6],  v1.z, a0); a1 = fmaf(S1[7],  v1.w, a1);
            a0 = fmaf(S1[8],  v2.x, a0); a1 = fmaf(S1[9],  v2.y, a1);
            a0 = fmaf(S1[10], v2.z, a0); a1 = fmaf(S1[11], v2.w, a1);
            a0 = fmaf(S1[12], v3.x, a0); a1 = fmaf(S1[13], v3.y, a1);
            a0 = fmaf(S1[14], v3.z, a0); a1 = fmaf(S1[15], v3.w, a1);
            a[u] = a0 + a1;
        }
        // softmax over the 16 lanes of this sample (xor 1,2,4,8 stays in half-warp)
#pragma unroll
        for (int u = 0; u < 7; u++) {
            float m = a[u];
            m = fmaxf(m, __shfl_xor_sync(0xffffffffu, m, 1));
            m = fmaxf(m, __shfl_xor_sync(0xffffffffu, m, 2));
            m = fmaxf(m, __shfl_xor_sync(0xffffffffu, m, 4));
            m = fmaxf(m, __shfl_xor_sync(0xffffffffu, m, 8));
            float e = __expf(a[u] - m);
            float sum = e;
            sum += __shfl_xor_sync(0xffffffffu, sum, 1);
            sum += __shfl_xor_sync(0xffffffffu, sum, 2);
            sum += __shfl_xor_sync(0xffffffffu, sum, 4);
            sum += __shfl_xor_sync(0xffffffffu, sum, 8);
            a[u] = e / sum;
        }
        __syncwarp();
#pragma unroll
        for (int u = 0; u < 7; u++) myrow[(sb + u) * 16 + t] = a[u];
        __syncwarp();
    }

    // ---------------- layer 2: chunks of 8 patches ----------------
    float S2[8];
#pragma unroll
    for (int e = 0; e < 8; e++) S2[e] = 0.f;
    const int d8 = t & 7;
    const int jp = t >> 3;

#pragma unroll 1
    for (int c0 = 0; c0 < 49; c0 += 8) {
        const int np = min(8, 49 - c0);
        __syncthreads();
        float vacc[4];
        const int s   = c0 + wrp;
        const int rV  = lane & 7;
        const int qtr = lane >> 3;
        if (wrp < np) {
            // pass A: 16 rows (8Q+8K) x parity-interleaved sample halves
            {
                const int row16 = lane & 15;
                const int parA  = lane >> 4;
                const bool isQ  = (row16 < 8);
                const int r = row16 & 7;
                const float4* W4 = reinterpret_cast<const float4*>(
                    (isQ ? WQ2 : WK2) + s * 128 + r * 16);
                float4 w0 = W4[0], w1 = W4[1], w2 = W4[2], w3 = W4[3];
                const float scl = isQ ? INV7 : 1.f;
                const int dst = (isQ ? SM_QB : (SM_KB + 8)) + wrp * 8 + r;
#pragma unroll 2
                for (int ii = 0; ii < 8; ii++) {
                    const int i = 2 * ii + parA;
                    const float4* tk = reinterpret_cast<const float4*>(&sh[SM_PB + i * 784 + s * 16]);
                    float acc = dot4(w3, tk[3], dot4(w2, tk[2], dot4(w1, tk[1], dot4(w0, tk[0], 0.f))));
                    sh[dst + i * 80] = acc * scl;
                }
            }
            // pass B: V rows x interleaved sample quarters (deferred)
            {
                const float4* W4 = reinterpret_cast<const float4*>(WV2 + s * 128 + rV * 16);
                float4 w0 = W4[0], w1 = W4[1], w2 = W4[2], w3 = W4[3];
#pragma unroll
                for (int ii = 0; ii < 4; ii++) {
                    const int i = 4 * ii + qtr;
                    const float4* tk = reinterpret_cast<const float4*>(&sh[SM_PB + i * 784 + s * 16]);
                    vacc[ii] = dot4(w3, tk[3], dot4(w2, tk[2], dot4(w1, tk[1], dot4(w0, tk[0], 0.f))));
                }
            }
        }
        __syncwarp();   // all tok2 reads complete before V2 overwrites
        if (wrp < np) {
#pragma unroll
            for (int ii = 0; ii < 4; ii++)
                sh[SM_PB + (4 * ii + qtr) * 784 + s * 16 + rV] = vacc[ii];
        }
        __syncthreads();
        // ---- G-phase: j split by parity (t<8 even j, t>=8 odd j) ----
#pragma unroll
        for (int jj = 0; jj < 4; jj++) {
            const int j = 2 * jj + jp;
            if (j < np) {
                float q2 = sh[SM_QB + ls * 80 + j * 8 + d8];
                const float4* kr = reinterpret_cast<const float4*>(&sh[SM_KB + 8 + ls * 80 + j * 8]);
                float4 k0 = kr[0], k1 = kr[1];
                S2[0] = fmaf(q2, k0.x, S2[0]); S2[1] = fmaf(q2, k0.y, S2[1]);
                S2[2] = fmaf(q2, k0.z, S2[2]); S2[3] = fmaf(q2, k0.w, S2[3]);
                S2[4] = fmaf(q2, k1.x, S2[4]); S2[5] = fmaf(q2, k1.y, S2[5]);
                S2[6] = fmaf(q2, k1.z, S2[6]); S2[7] = fmaf(q2, k1.w, S2[7]);
            }
        }
    }
    // combine gram partials across j-parity halves (same sample)
#pragma unroll
    for (int e = 0; e < 8; e++) S2[e] += __shfl_xor_sync(0xffffffffu, S2[e], 8);

    // ---------------- A2 + softmax2 fused: rows split by t-parity ----------------
#pragma unroll 1
    for (int u = 0; u < 25; u++) {
        const int s = 2 * u + jp;       // t<8 even rows, t>=8 odd rows
        float val = 0.f;
        if (s < 49) {
            const float4* vr = reinterpret_cast<const float4*>(&myrow[s * 16]);
            float4 v0 = vr[0], v1 = vr[1];
            float acc = 0.f;
            acc = fmaf(S2[0], v0.x, acc); acc = fmaf(S2[1], v0.y, acc);
            acc = fmaf(S2[2], v0.z, acc); acc = fmaf(S2[3], v0.w, acc);
            acc = fmaf(S2[4], v1.x, acc); acc = fmaf(S2[5], v1.y, acc);
            acc = fmaf(S2[6], v1.z, acc); acc = fmaf(S2[7], v1.w, acc);
            val = acc;
        }
        // softmax over the 8 lanes of this row (xor 1,2,4)
        float m = val;
        m = fmaxf(m, __shfl_xor_sync(0xffffffffu, m, 1));
        m = fmaxf(m, __shfl_xor_sync(0xffffffffu, m, 2));
        m = fmaxf(m, __shfl_xor_sync(0xffffffffu, m, 4));
        float e = __expf(val - m);
        float sum = e;
        sum += __shfl_xor_sync(0xffffffffu, sum, 1);
        sum += __shfl_xor_sync(0xffffffffu, sum, 2);
        sum += __shfl_xor_sync(0xffffffffu, sum, 4);
        if (s < 49) myrow[s * 16 + d8] = e / sum;   // shfl converged warp: reads done
    }
    __syncwarp();

    // ---------------- FC head: fc1w staged in two K-halves, stride 204 ----------------
    float acc = sh[SM_F1B + t];
    __syncthreads();
    for (int idx = tid; idx < 768; idx += NTHR) {    // 16 rows x 48 float4 (cols 0..191)
        int j = idx / 48, c4 = idx - j * 48;
        *reinterpret_cast<float4*>(&sh[SM_QB + j * 204 + c4 * 4]) =
            *reinterpret_cast<const float4*>(&fc1w[j * 392 + c4 * 4]);
    }
    __syncthreads();
#pragma unroll 1
    for (int s = 0; s < 24; s++) {
        float4 a0 = *reinterpret_cast<const float4*>(&myrow[s * 16]);
        float4 a1 = *reinterpret_cast<const float4*>(&myrow[s * 16 + 4]);
        float4 w0 = *reinterpret_cast<const float4*>(&sh[SM_QB + t * 204 + s * 8]);
        float4 w1 = *reinterpret_cast<const float4*>(&sh[SM_QB + t * 204 + s * 8 + 4]);
        acc = dot4(w0, a0, acc);
        acc = dot4(w1, a1, acc);
    }
    __syncthreads();
    for (int idx = tid; idx < 800; idx += NTHR) {    // 16 rows x 50 float4 (cols 192..391)
        int j = idx / 50, c4 = idx - j * 50;
        *reinterpret_cast<float4*>(&sh[SM_QB + j * 204 + c4 * 4]) =
            *reinterpret_cast<const float4*>(&fc1w[j * 392 + 192 + c4 * 4]);
    }
    __syncthreads();
#pragma unroll 1
    for (int s = 24; s < 49; s++) {
        float4 a0 = *reinterpret_cast<const float4*>(&myrow[s * 16]);
        float4 a1 = *reinterpret_cast<const float4*>(&myrow[s * 16 + 4]);
        float4 w0 = *reinterpret_cast<const float4*>(&sh[SM_QB + t * 204 + (s - 24) * 8]);
        float4 w1 = *reinterpret_cast<const float4*>(&sh[SM_QB + t * 204 + (s - 24) * 8 + 4]);
        acc = dot4(w0, a0, acc);
        acc = dot4(w1, a1, acc);
    }
    sh[SM_H + ls * 16 + t] = fmaxf(acc, 0.f);
    __syncwarp();

    {
        float lg = 0.f;
        if (t < 10) {
            const float4* w  = reinterpret_cast<const float4*>(&sh[SM_F2W + t * 16]);
            const float4* hh = reinterpret_cast<const float4*>(&sh[SM_H + ls * 16]);
            lg = dot4(w[0], hh[0], lg); lg = dot4(w[1], hh[1], lg);
            lg = dot4(w[2], hh[2], lg); lg = dot4(w[3], hh[3], lg);
            lg += sh[SM_F2B + t];
        }
        sh[SM_LG + ls * 16 + t] = lg;
    }
    __syncwarp();

    if (t == 0 && b < B) {
        const float* lrow = &sh[SM_LG + ls * 16];
        float m = lrow[0];
#pragma unroll
        for (int c = 1; c < 10; c++) m = fmaxf(m, lrow[c]);
        float ex[10], sum = 0.f;
#pragma unroll
        for (int c = 0; c < 10; c++) { ex[c] = __expf(lrow[c] - m); sum += ex[c]; }
        float inv = 1.f / sum;
        float* o = out + (size_t)b * 10;
#pragma unroll
        for (int c = 0; c < 10; c++) o[c] = ex[c] * inv;
    }
}

extern "C" void kernel_launch(void* const* d_in, const int* in_sizes, int n_in,
                              void* d_out, int out_size) {
    const float* x   = (const float*)d_in[0];
    const float* pe  = (const float*)d_in[1];
    const float* WQ1 = (const float*)d_in[2];
    const float* WK1 = (const float*)d_in[3];
    const float* WV1 = (const float*)d_in[4];
    const float* WQ2 = (const float*)d_in[5];
    const float* WK2 = (const float*)d_in[6];
    const float* WV2 = (const float*)d_in[7];
    const float* f1w = (const float*)d_in[8];
    const float* f1b = (const float*)d_in[9];
    const float* f2w = (const float*)d_in[10];
    const float* f2b = (const float*)d_in[11];
    float* out = (float*)d_out;

    int B = in_sizes[0] / (3 * 28 * 28);
    int grid = (B + GRP - 1) / GRP;
    size_t smem = (size_t)SM_TOT * sizeof(float);

    cudaFuncSetAttribute(vit_fused_kernel,
                         cudaFuncAttributeMaxDynamicSharedMemorySize, (int)smem);
    vit_fused_kernel<<<grid, NTHR, smem>>>(x, pe, WQ1, WK1, WV1, WQ2, WK2, WV2,
                                           f1w, f1b, f2w, f2b, out, B);
}

// round 12
// speedup vs baseline: 1.0634x; 1.0634x over previous
#include <cuda_runtime.h>
#include <math.h>

// ViT fused R12 = R11's LDS-traffic reductions + R10's smem softmax (revert
// the shfl-fused softmax that regressed R11).
//  - L1 pass A: merged Q+K weight rows per lane (tok LDS halved)
//  - parity-interleaved sample halves/quarters (bank-disjoint)
//  - QB/KB strides 144/80(+8), fc1w stride 204
//  - A1/A2 grouped writes + lane-per-row smem softmax (R10 style)

#define GRP  16
#define NTHR 256

static constexpr int SM_PB  = 0;        // 16*784 = 12544
static constexpr int SM_PE  = 12544;    // 784
static constexpr int SM_QB  = 13328;    // 2304 (16 x 144); fc1w staging 16x204=3264 spans QB+KB
static constexpr int SM_KB  = 15632;    // 2304
static constexpr int SM_F2W = 17936;    // 160
static constexpr int SM_F1B = 18096;    // 16
static constexpr int SM_F2B = 18112;    // 16
static constexpr int SM_H   = 18128;    // 256
static constexpr int SM_LG  = 18384;    // 256
static constexpr int SM_TOT = 18640;    // 74560 bytes -> 3 CTAs/SM

__device__ __forceinline__ float dot4(float4 w, float4 a, float acc) {
    acc = fmaf(w.x, a.x, acc); acc = fmaf(w.y, a.y, acc);
    acc = fmaf(w.z, a.z, acc); return fmaf(w.w, a.w, acc);
}

__global__ __launch_bounds__(NTHR, 3)
void vit_fused_kernel(
    const float* __restrict__ x, const float* __restrict__ pos_emb,
    const float* __restrict__ WQ1, const float* __restrict__ WK1, const float* __restrict__ WV1,
    const float* __restrict__ WQ2, const float* __restrict__ WK2, const float* __restrict__ WV2,
    const float* __restrict__ fc1w, const float* __restrict__ fc1b,
    const float* __restrict__ fc2w, const float* __restrict__ fc2b,
    float* __restrict__ out, int B)
{
    extern __shared__ float sh[];
    const int tid  = threadIdx.x;
    const int lane = tid & 31;
    const int wrp  = tid >> 5;          // 0..7 : patch slot in P-phases
    const int t    = tid & 15;          // dim within sample
    const int ls   = tid >> 4;          // sample slot
    const int b0   = blockIdx.x * GRP;
    const int b    = b0 + ls;
    const float INV7 = 0.14285714285714285f;
    float* myrow = &sh[SM_PB + ls * 784];

    // ---------------- phase 0: patchify + constants ----------------
    for (int idx = tid; idx < GRP * 784; idx += NTHR) {
        int lsi = idx / 784, pix = idx - lsi * 784;
        int bb = b0 + lsi;
        float g = 0.f;
        if (bb < B) {
            const float* xp = x + (size_t)bb * 2352 + pix;
            g = 0.299f * xp[0] + 0.587f * xp[784] + 0.114f * xp[1568];
        }
        int y = pix / 28, xx = pix - y * 28;
        sh[SM_PB + lsi * 784 + ((y >> 2) * 7 + (xx >> 2)) * 16 + (y & 3) * 4 + (xx & 3)] = g;
    }
    for (int idx = tid; idx < 784; idx += NTHR) sh[SM_PE + idx] = pos_emb[idx];
    if (tid < 160) sh[SM_F2W + tid] = fc2w[tid];
    if (tid < 16)  sh[SM_F1B + tid] = fc1b[tid];
    if (tid < 10)  sh[SM_F2B + tid] = fc2b[tid];

    // ---------------- layer 1: chunks of 8 patches ----------------
    float S1[16];
#pragma unroll
    for (int e = 0; e < 16; e++) S1[e] = 0.f;

#pragma unroll 1
    for (int c0 = 0; c0 < 49; c0 += 8) {
        const int np = min(8, 49 - c0);
        __syncthreads();
        float vacc[8];
        const int s   = c0 + wrp;
        const int row = lane & 15;
        const int par = lane >> 4;          // sample parity
        if (wrp < np) {
            const float4* pe4 = reinterpret_cast<const float4*>(&sh[SM_PE + s * 16]);
            float4 p0 = pe4[0], p1 = pe4[1], p2 = pe4[2], p3 = pe4[3];
            // ---- pass A: merged Q+K rows per lane; 8 samples (parity-interleaved) ----
            {
                const float4* Wq = reinterpret_cast<const float4*>(WQ1 + s * 512 + row * 32);
                const float4* Wk = reinterpret_cast<const float4*>(WK1 + s * 512 + row * 32);
                float4 q0 = Wq[0], q1 = Wq[1], q2 = Wq[2], q3 = Wq[3];
                float4 k0 = Wk[0], k1 = Wk[1], k2 = Wk[2], k3 = Wk[3];
                float peq = dot4(Wq[7], p3, dot4(Wq[6], p2, dot4(Wq[5], p1, dot4(Wq[4], p0, 0.f))));
                float pek = dot4(Wk[7], p3, dot4(Wk[6], p2, dot4(Wk[5], p1, dot4(Wk[4], p0, 0.f))));
#pragma unroll 2
                for (int ii = 0; ii < 8; ii++) {
                    const int i = 2 * ii + par;
                    const float4* tk = reinterpret_cast<const float4*>(&sh[SM_PB + i * 784 + s * 16]);
                    float4 a0 = tk[0], a1 = tk[1], a2 = tk[2], a3 = tk[3];
                    float q = dot4(q3, a3, dot4(q2, a2, dot4(q1, a1, dot4(q0, a0, peq))));
                    float k = dot4(k3, a3, dot4(k2, a2, dot4(k1, a1, dot4(k0, a0, pek))));
                    sh[SM_QB + i * 144 + wrp * 16 + row] = q * INV7;
                    sh[SM_KB + i * 144 + wrp * 16 + row] = k;
                }
            }
            // ---- pass B: V rows (deferred writes) ----
            {
                const float4* Wv = reinterpret_cast<const float4*>(WV1 + s * 512 + row * 32);
                float4 v0 = Wv[0], v1 = Wv[1], v2 = Wv[2], v3 = Wv[3];
                float pev = dot4(Wv[7], p3, dot4(Wv[6], p2, dot4(Wv[5], p1, dot4(Wv[4], p0, 0.f))));
#pragma unroll 2
                for (int ii = 0; ii < 8; ii++) {
                    const int i = 2 * ii + par;
                    const float4* tk = reinterpret_cast<const float4*>(&sh[SM_PB + i * 784 + s * 16]);
                    vacc[ii] = dot4(v3, tk[3], dot4(v2, tk[2], dot4(v1, tk[1], dot4(v0, tk[0], pev))));
                }
            }
        }
        __syncwarp();   // all patch-row reads complete before V overwrites
        if (wrp < np) {
#pragma unroll
            for (int ii = 0; ii < 8; ii++)
                sh[SM_PB + (2 * ii + par) * 784 + s * 16 + row] = vacc[ii];
        }
        __syncthreads();
        // ---- G-phase: warp = 2 samples ----
#pragma unroll 1
        for (int j = 0; j < np; j++) {
            float q = sh[SM_QB + ls * 144 + j * 16 + t];
            const float4* kr = reinterpret_cast<const float4*>(&sh[SM_KB + ls * 144 + j * 16]);
            float4 k0 = kr[0], k1 = kr[1], k2 = kr[2], k3 = kr[3];
            S1[0]  = fmaf(q, k0.x, S1[0]);  S1[1]  = fmaf(q, k0.y, S1[1]);
            S1[2]  = fmaf(q, k0.z, S1[2]);  S1[3]  = fmaf(q, k0.w, S1[3]);
            S1[4]  = fmaf(q, k1.x, S1[4]);  S1[5]  = fmaf(q, k1.y, S1[5]);
            S1[6]  = fmaf(q, k1.z, S1[6]);  S1[7]  = fmaf(q, k1.w, S1[7]);
            S1[8]  = fmaf(q, k2.x, S1[8]);  S1[9]  = fmaf(q, k2.y, S1[9]);
            S1[10] = fmaf(q, k2.z, S1[10]); S1[11] = fmaf(q, k2.w, S1[11]);
            S1[12] = fmaf(q, k3.x, S1[12]); S1[13] = fmaf(q, k3.y, S1[13]);
            S1[14] = fmaf(q, k3.z, S1[14]); S1[15] = fmaf(q, k3.w, S1[15]);
        }
    }

    // ---------------- A1: grouped compute -> syncwarp -> write (in place) ----------------
#pragma unroll 1
    for (int sb = 0; sb < 49; sb += 7) {
        float a[7];
#pragma unroll
        for (int u = 0; u < 7; u++) {
            const float4* vr = reinterpret_cast<const float4*>(&myrow[(sb + u) * 16]);
            float4 v0 = vr[0], v1 = vr[1], v2 = vr[2], v3 = vr[3];
            float a0 = 0.f, a1 = 0.f;
            a0 = fmaf(S1[0],  v0.x, a0); a1 = fmaf(S1[1],  v0.y, a1);
            a0 = fmaf(S1[2],  v0.z, a0); a1 = fmaf(S1[3],  v0.w, a1);
            a0 = fmaf(S1[4],  v1.x, a0); a1 = fmaf(S1[5],  v1.y, a1);
            a0 = fmaf(S1[6],  v1.z, a0); a1 = fmaf(S1[7],  v1.w, a1);
            a0 = fmaf(S1[8],  v2.x, a0); a1 = fmaf(S1[9],  v2.y, a1);
            a0 = fmaf(S1[10], v2.z, a0); a1 = fmaf(S1[11], v2.w, a1);
            a0 = fmaf(S1[12], v3.x, a0); a1 = fmaf(S1[13], v3.y, a1);
            a0 = fmaf(S1[14], v3.z, a0); a1 = fmaf(S1[15], v3.w, a1);
            a[u] = a0 + a1;
        }
        __syncwarp();
#pragma unroll
        for (int u = 0; u < 7; u++) myrow[(sb + u) * 16 + t] = a[u];
        __syncwarp();
    }

    // ---------------- softmax1 (lane-per-row, smem) ----------------
#pragma unroll 1
    for (int s = t; s < 49; s += 16) {
        float4* row = reinterpret_cast<float4*>(&myrow[s * 16]);
        float4 r0 = row[0], r1 = row[1], r2 = row[2], r3 = row[3];
        float m = fmaxf(fmaxf(fmaxf(r0.x, r0.y), fmaxf(r0.z, r0.w)),
                        fmaxf(fmaxf(r1.x, r1.y), fmaxf(r1.z, r1.w)));
        m = fmaxf(m, fmaxf(fmaxf(fmaxf(r2.x, r2.y), fmaxf(r2.z, r2.w)),
                           fmaxf(fmaxf(r3.x, r3.y), fmaxf(r3.z, r3.w))));
        r0.x = __expf(r0.x - m); r0.y = __expf(r0.y - m); r0.z = __expf(r0.z - m); r0.w = __expf(r0.w - m);
        r1.x = __expf(r1.x - m); r1.y = __expf(r1.y - m); r1.z = __expf(r1.z - m); r1.w = __expf(r1.w - m);
        r2.x = __expf(r2.x - m); r2.y = __expf(r2.y - m); r2.z = __expf(r2.z - m); r2.w = __expf(r2.w - m);
        r3.x = __expf(r3.x - m); r3.y = __expf(r3.y - m); r3.z = __expf(r3.z - m); r3.w = __expf(r3.w - m);
        float sum = (r0.x + r0.y + r0.z + r0.w) + (r1.x + r1.y + r1.z + r1.w)
                  + (r2.x + r2.y + r2.z + r2.w) + (r3.x + r3.y + r3.z + r3.w);
        float inv = 1.f / sum;
        r0.x *= inv; r0.y *= inv; r0.z *= inv; r0.w *= inv;
        r1.x *= inv; r1.y *= inv; r1.z *= inv; r1.w *= inv;
        r2.x *= inv; r2.y *= inv; r2.z *= inv; r2.w *= inv;
        r3.x *= inv; r3.y *= inv; r3.z *= inv; r3.w *= inv;
        row[0] = r0; row[1] = r1; row[2] = r2; row[3] = r3;
    }

    // ---------------- layer 2: chunks of 8 patches ----------------
    float S2[8];
#pragma unroll
    for (int e = 0; e < 8; e++) S2[e] = 0.f;
    const int d8 = t & 7;
    const int jp = t >> 3;

#pragma unroll 1
    for (int c0 = 0; c0 < 49; c0 += 8) {
        const int np = min(8, 49 - c0);
        __syncthreads();
        float vacc[4];
        const int s   = c0 + wrp;
        const int rV  = lane & 7;
        const int qtr = lane >> 3;
        if (wrp < np) {
            // pass A: 16 rows (8Q+8K) x parity-interleaved sample halves
            {
                const int row16 = lane & 15;
                const int parA  = lane >> 4;
                const bool isQ  = (row16 < 8);
                const int r = row16 & 7;
                const float4* W4 = reinterpret_cast<const float4*>(
                    (isQ ? WQ2 : WK2) + s * 128 + r * 16);
                float4 w0 = W4[0], w1 = W4[1], w2 = W4[2], w3 = W4[3];
                const float scl = isQ ? INV7 : 1.f;
                const int dst = (isQ ? SM_QB : (SM_KB + 8)) + wrp * 8 + r;
#pragma unroll 2
                for (int ii = 0; ii < 8; ii++) {
                    const int i = 2 * ii + parA;
                    const float4* tk = reinterpret_cast<const float4*>(&sh[SM_PB + i * 784 + s * 16]);
                    float acc = dot4(w3, tk[3], dot4(w2, tk[2], dot4(w1, tk[1], dot4(w0, tk[0], 0.f))));
                    sh[dst + i * 80] = acc * scl;
                }
            }
            // pass B: V rows x interleaved sample quarters (deferred)
            {
                const float4* W4 = reinterpret_cast<const float4*>(WV2 + s * 128 + rV * 16);
                float4 w0 = W4[0], w1 = W4[1], w2 = W4[2], w3 = W4[3];
#pragma unroll
                for (int ii = 0; ii < 4; ii++) {
                    const int i = 4 * ii + qtr;
                    const float4* tk = reinterpret_cast<const float4*>(&sh[SM_PB + i * 784 + s * 16]);
                    vacc[ii] = dot4(w3, tk[3], dot4(w2, tk[2], dot4(w1, tk[1], dot4(w0, tk[0], 0.f))));
                }
            }
        }
        __syncwarp();   // all tok2 reads complete before V2 overwrites
        if (wrp < np) {
#pragma unroll
            for (int ii = 0; ii < 4; ii++)
                sh[SM_PB + (4 * ii + qtr) * 784 + s * 16 + rV] = vacc[ii];
        }
        __syncthreads();
        // ---- G-phase: j split by parity (t<8 even j, t>=8 odd j) ----
#pragma unroll
        for (int jj = 0; jj < 4; jj++) {
            const int j = 2 * jj + jp;
            if (j < np) {
                float q2 = sh[SM_QB + ls * 80 + j * 8 + d8];
                const float4* kr = reinterpret_cast<const float4*>(&sh[SM_KB + 8 + ls * 80 + j * 8]);
                float4 k0 = kr[0], k1 = kr[1];
                S2[0] = fmaf(q2, k0.x, S2[0]); S2[1] = fmaf(q2, k0.y, S2[1]);
                S2[2] = fmaf(q2, k0.z, S2[2]); S2[3] = fmaf(q2, k0.w, S2[3]);
                S2[4] = fmaf(q2, k1.x, S2[4]); S2[5] = fmaf(q2, k1.y, S2[5]);
                S2[6] = fmaf(q2, k1.z, S2[6]); S2[7] = fmaf(q2, k1.w, S2[7]);
            }
        }
    }
    // combine gram partials across j-parity halves (same sample)
#pragma unroll
    for (int e = 0; e < 8; e++) S2[e] += __shfl_xor_sync(0xffffffffu, S2[e], 8);

    // ---------------- A2: grouped (t<8 computes), then smem softmax2 ----------------
#pragma unroll 1
    for (int sb = 0; sb < 49; sb += 7) {
        float a[7];
#pragma unroll
        for (int u = 0; u < 7; u++) {
            float acc = 0.f;
            if (t < 8) {
                const float4* vr = reinterpret_cast<const float4*>(&myrow[(sb + u) * 16]);
                float4 v0 = vr[0], v1 = vr[1];
                acc = fmaf(S2[0], v0.x, acc); acc = fmaf(S2[1], v0.y, acc);
                acc = fmaf(S2[2], v0.z, acc); acc = fmaf(S2[3], v0.w, acc);
                acc = fmaf(S2[4], v1.x, acc); acc = fmaf(S2[5], v1.y, acc);
                acc = fmaf(S2[6], v1.z, acc); acc = fmaf(S2[7], v1.w, acc);
            }
            a[u] = acc;
        }
        __syncwarp();
        if (t < 8) {
#pragma unroll
            for (int u = 0; u < 7; u++) myrow[(sb + u) * 16 + t] = a[u];
        }
        __syncwarp();
    }

    // ---------------- softmax2 (lane-per-row, smem) ----------------
#pragma unroll 1
    for (int s = t; s < 49; s += 16) {
        float4* row = reinterpret_cast<float4*>(&myrow[s * 16]);
        float4 r0 = row[0], r1 = row[1];
        float m = fmaxf(fmaxf(fmaxf(r0.x, r0.y), fmaxf(r0.z, r0.w)),
                        fmaxf(fmaxf(r1.x, r1.y), fmaxf(r1.z, r1.w)));
        r0.x = __expf(r0.x - m); r0.y = __expf(r0.y - m); r0.z = __expf(r0.z - m); r0.w = __expf(r0.w - m);
        r1.x = __expf(r1.x - m); r1.y = __expf(r1.y - m); r1.z = __expf(r1.z - m); r1.w = __expf(r1.w - m);
        float sum = (r0.x + r0.y + r0.z + r0.w) + (r1.x + r1.y + r1.z + r1.w);
        float inv = 1.f / sum;
        r0.x *= inv; r0.y *= inv; r0.z *= inv; r0.w *= inv;
        r1.x *= inv; r1.y *= inv; r1.z *= inv; r1.w *= inv;
        row[0] = r0; row[1] = r1;
    }

    // ---------------- FC head: fc1w staged in two K-halves, stride 204 ----------------
    float acc = sh[SM_F1B + t];
    __syncthreads();
    for (int idx = tid; idx < 768; idx += NTHR) {    // 16 rows x 48 float4 (cols 0..191)
        int j = idx / 48, c4 = idx - j * 48;
        *reinterpret_cast<float4*>(&sh[SM_QB + j * 204 + c4 * 4]) =
            *reinterpret_cast<const float4*>(&fc1w[j * 392 + c4 * 4]);
    }
    __syncthreads();
#pragma unroll 1
    for (int s = 0; s < 24; s++) {
        float4 a0 = *reinterpret_cast<const float4*>(&myrow[s * 16]);
        float4 a1 = *reinterpret_cast<const float4*>(&myrow[s * 16 + 4]);
        float4 w0 = *reinterpret_cast<const float4*>(&sh[SM_QB + t * 204 + s * 8]);
        float4 w1 = *reinterpret_cast<const float4*>(&sh[SM_QB + t * 204 + s * 8 + 4]);
        acc = dot4(w0, a0, acc);
        acc = dot4(w1, a1, acc);
    }
    __syncthreads();
    for (int idx = tid; idx < 800; idx += NTHR) {    // 16 rows x 50 float4 (cols 192..391)
        int j = idx / 50, c4 = idx - j * 50;
        *reinterpret_cast<float4*>(&sh[SM_QB + j * 204 + c4 * 4]) =
            *reinterpret_cast<const float4*>(&fc1w[j * 392 + 192 + c4 * 4]);
    }
    __syncthreads();
#pragma unroll 1
    for (int s = 24; s < 49; s++) {
        float4 a0 = *reinterpret_cast<const float4*>(&myrow[s * 16]);
        float4 a1 = *reinterpret_cast<const float4*>(&myrow[s * 16 + 4]);
        float4 w0 = *reinterpret_cast<const float4*>(&sh[SM_QB + t * 204 + (s - 24) * 8]);
        float4 w1 = *reinterpret_cast<const float4*>(&sh[SM_QB + t * 204 + (s - 24) * 8 + 4]);
        acc = dot4(w0, a0, acc);
        acc = dot4(w1, a1, acc);
    }
    sh[SM_H + ls * 16 + t] = fmaxf(acc, 0.f);
    __syncwarp();

    {
        float lg = 0.f;
        if (t < 10) {
            const float4* w  = reinterpret_cast<const float4*>(&sh[SM_F2W + t * 16]);
            const float4* hh = reinterpret_cast<const float4*>(&sh[SM_H + ls * 16]);
            lg = dot4(w[0], hh[0], lg); lg = dot4(w[1], hh[1], lg);
            lg = dot4(w[2], hh[2], lg); lg = dot4(w[3], hh[3], lg);
            lg += sh[SM_F2B + t];
        }
        sh[SM_LG + ls * 16 + t] = lg;
    }
    __syncwarp();

    if (t == 0 && b < B) {
        const float* lrow = &sh[SM_LG + ls * 16];
        float m = lrow[0];
#pragma unroll
        for (int c = 1; c < 10; c++) m = fmaxf(m, lrow[c]);
        float ex[10], sum = 0.f;
#pragma unroll
        for (int c = 0; c < 10; c++) { ex[c] = __expf(lrow[c] - m); sum += ex[c]; }
        float inv = 1.f / sum;
        float* o = out + (size_t)b * 10;
#pragma unroll
        for (int c = 0; c < 10; c++) o[c] = ex[c] * inv;
    }
}

extern "C" void kernel_launch(void* const* d_in, const int* in_sizes, int n_in,
                              void* d_out, int out_size) {
    const float* x   = (const float*)d_in[0];
    const float* pe  = (const float*)d_in[1];
    const float* WQ1 = (const float*)d_in[2];
    const float* WK1 = (const float*)d_in[3];
    const float* WV1 = (const float*)d_in[4];
    const float* WQ2 = (const float*)d_in[5];
    const float* WK2 = (const float*)d_in[6];
    const float* WV2 = (const float*)d_in[7];
    const float* f1w = (const float*)d_in[8];
    const float* f1b = (const float*)d_in[9];
    const float* f2w = (const float*)d_in[10];
    const float* f2b = (const float*)d_in[11];
    float* out = (float*)d_out;

    int B = in_sizes[0] / (3 * 28 * 28);
    int grid = (B + GRP - 1) / GRP;
    size_t smem = (size_t)SM_TOT * sizeof(float);

    cudaFuncSetAttribute(vit_fused_kernel,
                         cudaFuncAttributeMaxDynamicSharedMemorySize, (int)smem);
    vit_fused_kernel<<<grid, NTHR, smem>>>(x, pe, WQ1, WK1, WV1, WQ2, WK2, WV2,
                                           f1w, f1b, f2w, f2b, out, B);
}

// round 14
// speedup vs baseline: 1.1869x; 1.1161x over previous
#include <cuda_runtime.h>
#include <math.h>

// ViT fused R13 = R10 (best, 317.9us) + pure bank-padding fixes only:
//   - QB/KB stride 128->144 (L1), 64->80 (L2); KB base ≡ QB+16 (L1 stores),
//     KB2 base ≡ QB+24 (L2 stores/loads 4-group disjoint)
//   - L1 V-pass sample parity (2ii+par), L2 V-pass 4ii+qtr (4-way -> 2-way)
//   - fc1w staging stride 200->204 (4-way -> 2-way)
// No instruction-count or register changes vs R10.

#define GRP  16
#define NTHR 256

static constexpr int SM_PB  = 0;        // 16*784 = 12544
static constexpr int SM_PE  = 12544;    // 784
static constexpr int SM_QB  = 13328;    // 16*144 = 2304 (ends 15632); QB%32 = 16
static constexpr int SM_KB  = 15648;    // pad 16 -> KB%32 = 0 (= QB+16 mod 32); 2304 (ends 17952)
static constexpr int SM_F2W = 17952;    // 160
static constexpr int SM_F1B = 18112;    // 16
static constexpr int SM_F2B = 18128;    // 16
static constexpr int SM_H   = 18144;    // 256
static constexpr int SM_LG  = 18400;    // 256
static constexpr int SM_TOT = 18656;    // 74624 B -> 3 CTAs/SM
static constexpr int KB2    = SM_KB + 24;  // L2 K staging base (%32 = 24 = QB+8 group)

__device__ __forceinline__ float dot4(float4 w, float4 a, float acc) {
    acc = fmaf(w.x, a.x, acc); acc = fmaf(w.y, a.y, acc);
    acc = fmaf(w.z, a.z, acc); return fmaf(w.w, a.w, acc);
}

__global__ __launch_bounds__(NTHR, 3)
void vit_fused_kernel(
    const float* __restrict__ x, const float* __restrict__ pos_emb,
    const float* __restrict__ WQ1, const float* __restrict__ WK1, const float* __restrict__ WV1,
    const float* __restrict__ WQ2, const float* __restrict__ WK2, const float* __restrict__ WV2,
    const float* __restrict__ fc1w, const float* __restrict__ fc1b,
    const float* __restrict__ fc2w, const float* __restrict__ fc2b,
    float* __restrict__ out, int B)
{
    extern __shared__ float sh[];
    const int tid  = threadIdx.x;
    const int lane = tid & 31;
    const int wrp  = tid >> 5;          // 0..7 : patch slot in P-phases
    const int t    = tid & 15;          // dim within sample
    const int ls   = tid >> 4;          // sample slot
    const int b0   = blockIdx.x * GRP;
    const int b    = b0 + ls;
    const float INV7 = 0.14285714285714285f;
    float* myrow = &sh[SM_PB + ls * 784];

    // ---------------- phase 0: patchify + constants ----------------
    for (int idx = tid; idx < GRP * 784; idx += NTHR) {
        int lsi = idx / 784, pix = idx - lsi * 784;
        int bb = b0 + lsi;
        float g = 0.f;
        if (bb < B) {
            const float* xp = x + (size_t)bb * 2352 + pix;
            g = 0.299f * xp[0] + 0.587f * xp[784] + 0.114f * xp[1568];
        }
        int y = pix / 28, xx = pix - y * 28;
        sh[SM_PB + lsi * 784 + ((y >> 2) * 7 + (xx >> 2)) * 16 + (y & 3) * 4 + (xx & 3)] = g;
    }
    for (int idx = tid; idx < 784; idx += NTHR) sh[SM_PE + idx] = pos_emb[idx];
    if (tid < 160) sh[SM_F2W + tid] = fc2w[tid];
    if (tid < 16)  sh[SM_F1B + tid] = fc1b[tid];
    if (tid < 10)  sh[SM_F2B + tid] = fc2b[tid];

    // ---------------- layer 1: chunks of 8 patches ----------------
    float S1[16];
#pragma unroll
    for (int e = 0; e < 16; e++) S1[e] = 0.f;

#pragma unroll 1
    for (int c0 = 0; c0 < 49; c0 += 8) {
        const int np = min(8, 49 - c0);
        __syncthreads();
        float vacc[8];
        const int s   = c0 + wrp;
        const int row = lane & 15;
        const int par = lane >> 4;          // sample parity for V pass
        // ---- P-phase ----
        if (wrp < np) {
            const float4* pe4 = reinterpret_cast<const float4*>(&sh[SM_PE + s * 16]);
            float4 p0 = pe4[0], p1 = pe4[1], p2 = pe4[2], p3 = pe4[3];
            // pass A: lanes 0-15 Q rows, 16-31 K rows; all 16 samples (broadcast tok)
            {
                const float* Wp = ((lane < 16) ? WQ1 : WK1) + s * 512 + row * 32;
                const float4* W4 = reinterpret_cast<const float4*>(Wp);
                float4 w0 = W4[0], w1 = W4[1], w2 = W4[2], w3 = W4[3];
                float pe_acc = dot4(W4[7], p3, dot4(W4[6], p2, dot4(W4[5], p1, dot4(W4[4], p0, 0.f))));
                const float scl = (lane < 16) ? INV7 : 1.f;
                const int dst = ((lane < 16) ? SM_QB : SM_KB) + wrp * 16 + row;
#pragma unroll 4
                for (int i = 0; i < 16; i++) {
                    const float4* tk = reinterpret_cast<const float4*>(&sh[SM_PB + i * 784 + s * 16]);
                    float acc = dot4(w3, tk[3], dot4(w2, tk[2], dot4(w1, tk[1], dot4(w0, tk[0], pe_acc))));
                    sh[dst + i * 144] = acc * scl;
                }
            }
            // pass B: V row = lane&15, sample parity split (bank-disjoint rows)
            {
                const float4* W4 = reinterpret_cast<const float4*>(WV1 + s * 512 + row * 32);
                float4 w0 = W4[0], w1 = W4[1], w2 = W4[2], w3 = W4[3];
                float pe_acc = dot4(W4[7], p3, dot4(W4[6], p2, dot4(W4[5], p1, dot4(W4[4], p0, 0.f))));
#pragma unroll 2
                for (int ii = 0; ii < 8; ii++) {
                    const int i = 2 * ii + par;
                    const float4* tk = reinterpret_cast<const float4*>(&sh[SM_PB + i * 784 + s * 16]);
                    vacc[ii] = dot4(w3, tk[3], dot4(w2, tk[2], dot4(w1, tk[1], dot4(w0, tk[0], pe_acc))));
                }
            }
        }
        __syncwarp();   // all patch-row reads complete before V overwrites
        if (wrp < np) {
#pragma unroll
            for (int ii = 0; ii < 8; ii++)
                sh[SM_PB + (2 * ii + par) * 784 + s * 16 + row] = vacc[ii];
        }
        __syncthreads();
        // ---- G-phase: warp = 2 samples, conflict-free via stride 144 ----
#pragma unroll 1
        for (int j = 0; j < np; j++) {
            float q = sh[SM_QB + ls * 144 + j * 16 + t];
            const float4* kr = reinterpret_cast<const float4*>(&sh[SM_KB + ls * 144 + j * 16]);
            float4 k0 = kr[0], k1 = kr[1], k2 = kr[2], k3 = kr[3];
            S1[0]  = fmaf(q, k0.x, S1[0]);  S1[1]  = fmaf(q, k0.y, S1[1]);
            S1[2]  = fmaf(q, k0.z, S1[2]);  S1[3]  = fmaf(q, k0.w, S1[3]);
            S1[4]  = fmaf(q, k1.x, S1[4]);  S1[5]  = fmaf(q, k1.y, S1[5]);
            S1[6]  = fmaf(q, k1.z, S1[6]);  S1[7]  = fmaf(q, k1.w, S1[7]);
            S1[8]  = fmaf(q, k2.x, S1[8]);  S1[9]  = fmaf(q, k2.y, S1[9]);
            S1[10] = fmaf(q, k2.z, S1[10]); S1[11] = fmaf(q, k2.w, S1[11]);
            S1[12] = fmaf(q, k3.x, S1[12]); S1[13] = fmaf(q, k3.y, S1[13]);
            S1[14] = fmaf(q, k3.z, S1[14]); S1[15] = fmaf(q, k3.w, S1[15]);
        }
    }

    // ---------------- A1: grouped compute -> syncwarp -> write (in place) ----------------
#pragma unroll 1
    for (int sb = 0; sb < 49; sb += 7) {
        float a[7];
#pragma unroll
        for (int u = 0; u < 7; u++) {
            const float4* vr = reinterpret_cast<const float4*>(&myrow[(sb + u) * 16]);
            float4 v0 = vr[0], v1 = vr[1], v2 = vr[2], v3 = vr[3];
            float a0 = 0.f, a1 = 0.f;
            a0 = fmaf(S1[0],  v0.x, a0); a1 = fmaf(S1[1],  v0.y, a1);
            a0 = fmaf(S1[2],  v0.z, a0); a1 = fmaf(S1[3],  v0.w, a1);
            a0 = fmaf(S1[4],  v1.x, a0); a1 = fmaf(S1[5],  v1.y, a1);
            a0 = fmaf(S1[6],  v1.z, a0); a1 = fmaf(S1[7],  v1.w, a1);
            a0 = fmaf(S1[8],  v2.x, a0); a1 = fmaf(S1[9],  v2.y, a1);
            a0 = fmaf(S1[10], v2.z, a0); a1 = fmaf(S1[11], v2.w, a1);
            a0 = fmaf(S1[12], v3.x, a0); a1 = fmaf(S1[13], v3.y, a1);
            a0 = fmaf(S1[14], v3.z, a0); a1 = fmaf(S1[15], v3.w, a1);
            a[u] = a0 + a1;
        }
        __syncwarp();
#pragma unroll
        for (int u = 0; u < 7; u++) myrow[(sb + u) * 16 + t] = a[u];
        __syncwarp();
    }

    // ---------------- softmax1 (lane-per-row, smem) ----------------
#pragma unroll 1
    for (int s = t; s < 49; s += 16) {
        float4* row = reinterpret_cast<float4*>(&myrow[s * 16]);
        float4 r0 = row[0], r1 = row[1], r2 = row[2], r3 = row[3];
        float m = fmaxf(fmaxf(fmaxf(r0.x, r0.y), fmaxf(r0.z, r0.w)),
                        fmaxf(fmaxf(r1.x, r1.y), fmaxf(r1.z, r1.w)));
        m = fmaxf(m, fmaxf(fmaxf(fmaxf(r2.x, r2.y), fmaxf(r2.z, r2.w)),
                           fmaxf(fmaxf(r3.x, r3.y), fmaxf(r3.z, r3.w))));
        r0.x = __expf(r0.x - m); r0.y = __expf(r0.y - m); r0.z = __expf(r0.z - m); r0.w = __expf(r0.w - m);
        r1.x = __expf(r1.x - m); r1.y = __expf(r1.y - m); r1.z = __expf(r1.z - m); r1.w = __expf(r1.w - m);
        r2.x = __expf(r2.x - m); r2.y = __expf(r2.y - m); r2.z = __expf(r2.z - m); r2.w = __expf(r2.w - m);
        r3.x = __expf(r3.x - m); r3.y = __expf(r3.y - m); r3.z = __expf(r3.z - m); r3.w = __expf(r3.w - m);
        float sum = (r0.x + r0.y + r0.z + r0.w) + (r1.x + r1.y + r1.z + r1.w)
                  + (r2.x + r2.y + r2.z + r2.w) + (r3.x + r3.y + r3.z + r3.w);
        float inv = 1.f / sum;
        r0.x *= inv; r0.y *= inv; r0.z *= inv; r0.w *= inv;
        r1.x *= inv; r1.y *= inv; r1.z *= inv; r1.w *= inv;
        r2.x *= inv; r2.y *= inv; r2.z *= inv; r2.w *= inv;
        r3.x *= inv; r3.y *= inv; r3.z *= inv; r3.w *= inv;
        row[0] = r0; row[1] = r1; row[2] = r2; row[3] = r3;
    }

    // ---------------- layer 2: chunks of 8 patches ----------------
    float S2[8];
#pragma unroll
    for (int e = 0; e < 8; e++) S2[e] = 0.f;

#pragma unroll 1
    for (int c0 = 0; c0 < 49; c0 += 8) {
        const int np = min(8, 49 - c0);
        __syncthreads();
        float vacc[4];
        const int s   = c0 + wrp;
        const int rV  = lane & 7;
        const int qtr = lane >> 3;          // V-pass sample quarter
        if (wrp < np) {
            // pass A: 16 rows (8Q+8K) x parity-split sample halves -> full 32 lanes
            {
                const int row16 = lane & 15;
                const int parA  = lane >> 4;
                const bool isQ  = (row16 < 8);
                const int r = row16 & 7;
                const float4* W4 = reinterpret_cast<const float4*>(
                    (isQ ? WQ2 : WK2) + s * 128 + r * 16);
                float4 w0 = W4[0], w1 = W4[1], w2 = W4[2], w3 = W4[3];
                const float scl = isQ ? INV7 : 1.f;
                const int dst = (isQ ? SM_QB : KB2) + wrp * 8 + r;
#pragma unroll 2
                for (int ii = 0; ii < 8; ii++) {
                    const int i = 2 * ii + parA;
                    const float4* tk = reinterpret_cast<const float4*>(&sh[SM_PB + i * 784 + s * 16]);
                    float acc = dot4(w3, tk[3], dot4(w2, tk[2], dot4(w1, tk[1], dot4(w0, tk[0], 0.f))));
                    sh[dst + i * 80] = acc * scl;
                }
            }
            // pass B: V rows x interleaved sample quarters (deferred)
            {
                const float4* W4 = reinterpret_cast<const float4*>(WV2 + s * 128 + rV * 16);
                float4 w0 = W4[0], w1 = W4[1], w2 = W4[2], w3 = W4[3];
#pragma unroll
                for (int ii = 0; ii < 4; ii++) {
                    const int i = 4 * ii + qtr;
                    const float4* tk = reinterpret_cast<const float4*>(&sh[SM_PB + i * 784 + s * 16]);
                    vacc[ii] = dot4(w3, tk[3], dot4(w2, tk[2], dot4(w1, tk[1], dot4(w0, tk[0], 0.f))));
                }
            }
        }
        __syncwarp();   // all tok2 reads complete before V2 overwrites
        if (wrp < np) {
#pragma unroll
            for (int ii = 0; ii < 4; ii++)
                sh[SM_PB + (4 * ii + qtr) * 784 + s * 16 + rV] = vacc[ii];
        }
        __syncthreads();
        // ---- G-phase (t<8 active), stride 80 conflict-free ----
        if (t < 8) {
#pragma unroll 1
            for (int j = 0; j < np; j++) {
                float q2 = sh[SM_QB + ls * 80 + j * 8 + t];
                const float4* kr = reinterpret_cast<const float4*>(&sh[KB2 + ls * 80 + j * 8]);
                float4 k0 = kr[0], k1 = kr[1];
                S2[0] = fmaf(q2, k0.x, S2[0]); S2[1] = fmaf(q2, k0.y, S2[1]);
                S2[2] = fmaf(q2, k0.z, S2[2]); S2[3] = fmaf(q2, k0.w, S2[3]);
                S2[4] = fmaf(q2, k1.x, S2[4]); S2[5] = fmaf(q2, k1.y, S2[5]);
                S2[6] = fmaf(q2, k1.z, S2[6]); S2[7] = fmaf(q2, k1.w, S2[7]);
            }
        }
    }

    // ---------------- A2: grouped (t<8 computes), in place ----------------
#pragma unroll 1
    for (int sb = 0; sb < 49; sb += 7) {
        float a[7];
#pragma unroll
        for (int u = 0; u < 7; u++) {
            float acc = 0.f;
            if (t < 8) {
                const float4* vr = reinterpret_cast<const float4*>(&myrow[(sb + u) * 16]);
                float4 v0 = vr[0], v1 = vr[1];
                acc = fmaf(S2[0], v0.x, acc); acc = fmaf(S2[1], v0.y, acc);
                acc = fmaf(S2[2], v0.z, acc); acc = fmaf(S2[3], v0.w, acc);
                acc = fmaf(S2[4], v1.x, acc); acc = fmaf(S2[5], v1.y, acc);
                acc = fmaf(S2[6], v1.z, acc); acc = fmaf(S2[7], v1.w, acc);
            }
            a[u] = acc;
        }
        __syncwarp();
        if (t < 8) {
#pragma unroll
            for (int u = 0; u < 7; u++) myrow[(sb + u) * 16 + t] = a[u];
        }
        __syncwarp();
    }

    // ---------------- softmax2 (lane-per-row, smem) ----------------
#pragma unroll 1
    for (int s = t; s < 49; s += 16) {
        float4* row = reinterpret_cast<float4*>(&myrow[s * 16]);
        float4 r0 = row[0], r1 = row[1];
        float m = fmaxf(fmaxf(fmaxf(r0.x, r0.y), fmaxf(r0.z, r0.w)),
                        fmaxf(fmaxf(r1.x, r1.y), fmaxf(r1.z, r1.w)));
        r0.x = __expf(r0.x - m); r0.y = __expf(r0.y - m); r0.z = __expf(r0.z - m); r0.w = __expf(r0.w - m);
        r1.x = __expf(r1.x - m); r1.y = __expf(r1.y - m); r1.z = __expf(r1.z - m); r1.w = __expf(r1.w - m);
        float sum = (r0.x + r0.y + r0.z + r0.w) + (r1.x + r1.y + r1.z + r1.w);
        float inv = 1.f / sum;
        r0.x *= inv; r0.y *= inv; r0.z *= inv; r0.w *= inv;
        r1.x *= inv; r1.y *= inv; r1.z *= inv; r1.w *= inv;
        row[0] = r0; row[1] = r1;
    }

    // ---------------- FC head: fc1w staged in two K-halves, stride 204 ----------------
    float acc = sh[SM_F1B + t];
    __syncthreads();
    for (int idx = tid; idx < 768; idx += NTHR) {    // 16 rows x 48 float4 (cols 0..191)
        int j = idx / 48, c4 = idx - j * 48;
        *reinterpret_cast<float4*>(&sh[SM_QB + j * 204 + c4 * 4]) =
            *reinterpret_cast<const float4*>(&fc1w[j * 392 + c4 * 4]);
    }
    __syncthreads();
#pragma unroll 1
    for (int s = 0; s < 24; s++) {
        float4 a0 = *reinterpret_cast<const float4*>(&myrow[s * 16]);
        float4 a1 = *reinterpret_cast<const float4*>(&myrow[s * 16 + 4]);
        float4 w0 = *reinterpret_cast<const float4*>(&sh[SM_QB + t * 204 + s * 8]);
        float4 w1 = *reinterpret_cast<const float4*>(&sh[SM_QB + t * 204 + s * 8 + 4]);
        acc = dot4(w0, a0, acc);
        acc = dot4(w1, a1, acc);
    }
    __syncthreads();
    for (int idx = tid; idx < 800; idx += NTHR) {    // 16 rows x 50 float4 (cols 192..391)
        int j = idx / 50, c4 = idx - j * 50;
        *reinterpret_cast<float4*>(&sh[SM_QB + j * 204 + c4 * 4]) =
            *reinterpret_cast<const float4*>(&fc1w[j * 392 + 192 + c4 * 4]);
    }
    __syncthreads();
#pragma unroll 1
    for (int s = 24; s < 49; s++) {
        float4 a0 = *reinterpret_cast<const float4*>(&myrow[s * 16]);
        float4 a1 = *reinterpret_cast<const float4*>(&myrow[s * 16 + 4]);
        float4 w0 = *reinterpret_cast<const float4*>(&sh[SM_QB + t * 204 + (s - 24) * 8]);
        float4 w1 = *reinterpret_cast<const float4*>(&sh[SM_QB + t * 204 + (s - 24) * 8 + 4]);
        acc = dot4(w0, a0, acc);
        acc = dot4(w1, a1, acc);
    }
    sh[SM_H + ls * 16 + t] = fmaxf(acc, 0.f);
    __syncwarp();

    {
        float lg = 0.f;
        if (t < 10) {
            const float4* w  = reinterpret_cast<const float4*>(&sh[SM_F2W + t * 16]);
            const float4* hh = reinterpret_cast<const float4*>(&sh[SM_H + ls * 16]);
            lg = dot4(w[0], hh[0], lg); lg = dot4(w[1], hh[1], lg);
            lg = dot4(w[2], hh[2], lg); lg = dot4(w[3], hh[3], lg);
            lg += sh[SM_F2B + t];
        }
        sh[SM_LG + ls * 16 + t] = lg;
    }
    __syncwarp();

    if (t == 0 && b < B) {
        const float* lrow = &sh[SM_LG + ls * 16];
        float m = lrow[0];
#pragma unroll
        for (int c = 1; c < 10; c++) m = fmaxf(m, lrow[c]);
        float ex[10], sum = 0.f;
#pragma unroll
        for (int c = 0; c < 10; c++) { ex[c] = __expf(lrow[c] - m); sum += ex[c]; }
        float inv = 1.f / sum;
        float* o = out + (size_t)b * 10;
#pragma unroll
        for (int c = 0; c < 10; c++) o[c] = ex[c] * inv;
    }
}

extern "C" void kernel_launch(void* const* d_in, const int* in_sizes, int n_in,
                              void* d_out, int out_size) {
    const float* x   = (const float*)d_in[0];
    const float* pe  = (const float*)d_in[1];
    const float* WQ1 = (const float*)d_in[2];
    const float* WK1 = (const float*)d_in[3];
    const float* WV1 = (const float*)d_in[4];
    const float* WQ2 = (const float*)d_in[5];
    const float* WK2 = (const float*)d_in[6];
    const float* WV2 = (const float*)d_in[7];
    const float* f1w = (const float*)d_in[8];
    const float* f1b = (const float*)d_in[9];
    const float* f2w = (const float*)d_in[10];
    const float* f2b = (const float*)d_in[11];
    float* out = (float*)d_out;

    int B = in_sizes[0] / (3 * 28 * 28);
    int grid = (B + GRP - 1) / GRP;
    size_t smem = (size_t)SM_TOT * sizeof(float);

    cudaFuncSetAttribute(vit_fused_kernel,
                         cudaFuncAttributeMaxDynamicSharedMemorySize, (int)smem);
    vit_fused_kernel<<<grid, NTHR, smem>>>(x, pe, WQ1, WK1, WV1, WQ2, WK2, WV2,
                                           f1w, f1b, f2w, f2b, out, B);
}

// round 15
// speedup vs baseline: 1.2544x; 1.0569x over previous
#include <cuda_runtime.h>
#include <math.h>

// ViT fused R15 = R13 (best, 297.3us) +
//   (a) quadrant-rotated softmax1/2 access (16-way -> ~4-way conflicts)
//   (b) G2 j-parity split across lane halves + xor-8 combine (halves G2 work)
//   (c) A2 row-parity split across lane halves (49 -> 25 iters/lane)

#define GRP  16
#define NTHR 256

static constexpr int SM_PB  = 0;        // 16*784 = 12544
static constexpr int SM_PE  = 12544;    // 784
static constexpr int SM_QB  = 13328;    // 16*144 = 2304; QB%32 = 16
static constexpr int SM_KB  = 15648;    // KB%32 = 0
static constexpr int SM_F2W = 17952;    // 160
static constexpr int SM_F1B = 18112;    // 16
static constexpr int SM_F2B = 18128;    // 16
static constexpr int SM_H   = 18144;    // 256
static constexpr int SM_LG  = 18400;    // 256
static constexpr int SM_TOT = 18656;    // 74624 B -> 3 CTAs/SM
static constexpr int KB2    = SM_KB + 24;

__device__ __forceinline__ float dot4(float4 w, float4 a, float acc) {
    acc = fmaf(w.x, a.x, acc); acc = fmaf(w.y, a.y, acc);
    acc = fmaf(w.z, a.z, acc); return fmaf(w.w, a.w, acc);
}

__global__ __launch_bounds__(NTHR, 3)
void vit_fused_kernel(
    const float* __restrict__ x, const float* __restrict__ pos_emb,
    const float* __restrict__ WQ1, const float* __restrict__ WK1, const float* __restrict__ WV1,
    const float* __restrict__ WQ2, const float* __restrict__ WK2, const float* __restrict__ WV2,
    const float* __restrict__ fc1w, const float* __restrict__ fc1b,
    const float* __restrict__ fc2w, const float* __restrict__ fc2b,
    float* __restrict__ out, int B)
{
    extern __shared__ float sh[];
    const int tid  = threadIdx.x;
    const int lane = tid & 31;
    const int wrp  = tid >> 5;          // 0..7 : patch slot in P-phases
    const int t    = tid & 15;          // dim within sample
    const int ls   = tid >> 4;          // sample slot
    const int b0   = blockIdx.x * GRP;
    const int b    = b0 + ls;
    const float INV7 = 0.14285714285714285f;
    float* myrow = &sh[SM_PB + ls * 784];

    // ---------------- phase 0: patchify + constants ----------------
    for (int idx = tid; idx < GRP * 784; idx += NTHR) {
        int lsi = idx / 784, pix = idx - lsi * 784;
        int bb = b0 + lsi;
        float g = 0.f;
        if (bb < B) {
            const float* xp = x + (size_t)bb * 2352 + pix;
            g = 0.299f * xp[0] + 0.587f * xp[784] + 0.114f * xp[1568];
        }
        int y = pix / 28, xx = pix - y * 28;
        sh[SM_PB + lsi * 784 + ((y >> 2) * 7 + (xx >> 2)) * 16 + (y & 3) * 4 + (xx & 3)] = g;
    }
    for (int idx = tid; idx < 784; idx += NTHR) sh[SM_PE + idx] = pos_emb[idx];
    if (tid < 160) sh[SM_F2W + tid] = fc2w[tid];
    if (tid < 16)  sh[SM_F1B + tid] = fc1b[tid];
    if (tid < 10)  sh[SM_F2B + tid] = fc2b[tid];

    // ---------------- layer 1: chunks of 8 patches ----------------
    float S1[16];
#pragma unroll
    for (int e = 0; e < 16; e++) S1[e] = 0.f;

#pragma unroll 1
    for (int c0 = 0; c0 < 49; c0 += 8) {
        const int np = min(8, 49 - c0);
        __syncthreads();
        float vacc[8];
        const int s   = c0 + wrp;
        const int row = lane & 15;
        const int par = lane >> 4;          // sample parity for V pass
        // ---- P-phase ----
        if (wrp < np) {
            const float4* pe4 = reinterpret_cast<const float4*>(&sh[SM_PE + s * 16]);
            float4 p0 = pe4[0], p1 = pe4[1], p2 = pe4[2], p3 = pe4[3];
            // pass A: lanes 0-15 Q rows, 16-31 K rows; all 16 samples (broadcast tok)
            {
                const float* Wp = ((lane < 16) ? WQ1 : WK1) + s * 512 + row * 32;
                const float4* W4 = reinterpret_cast<const float4*>(Wp);
                float4 w0 = W4[0], w1 = W4[1], w2 = W4[2], w3 = W4[3];
                float pe_acc = dot4(W4[7], p3, dot4(W4[6], p2, dot4(W4[5], p1, dot4(W4[4], p0, 0.f))));
                const float scl = (lane < 16) ? INV7 : 1.f;
                const int dst = ((lane < 16) ? SM_QB : SM_KB) + wrp * 16 + row;
#pragma unroll 4
                for (int i = 0; i < 16; i++) {
                    const float4* tk = reinterpret_cast<const float4*>(&sh[SM_PB + i * 784 + s * 16]);
                    float acc = dot4(w3, tk[3], dot4(w2, tk[2], dot4(w1, tk[1], dot4(w0, tk[0], pe_acc))));
                    sh[dst + i * 144] = acc * scl;
                }
            }
            // pass B: V row = lane&15, sample parity split (bank-disjoint rows)
            {
                const float4* W4 = reinterpret_cast<const float4*>(WV1 + s * 512 + row * 32);
                float4 w0 = W4[0], w1 = W4[1], w2 = W4[2], w3 = W4[3];
                float pe_acc = dot4(W4[7], p3, dot4(W4[6], p2, dot4(W4[5], p1, dot4(W4[4], p0, 0.f))));
#pragma unroll 2
                for (int ii = 0; ii < 8; ii++) {
                    const int i = 2 * ii + par;
                    const float4* tk = reinterpret_cast<const float4*>(&sh[SM_PB + i * 784 + s * 16]);
                    vacc[ii] = dot4(w3, tk[3], dot4(w2, tk[2], dot4(w1, tk[1], dot4(w0, tk[0], pe_acc))));
                }
            }
        }
        __syncwarp();   // all patch-row reads complete before V overwrites
        if (wrp < np) {
#pragma unroll
            for (int ii = 0; ii < 8; ii++)
                sh[SM_PB + (2 * ii + par) * 784 + s * 16 + row] = vacc[ii];
        }
        __syncthreads();
        // ---- G-phase: warp = 2 samples, conflict-free via stride 144 ----
#pragma unroll 1
        for (int j = 0; j < np; j++) {
            float q = sh[SM_QB + ls * 144 + j * 16 + t];
            const float4* kr = reinterpret_cast<const float4*>(&sh[SM_KB + ls * 144 + j * 16]);
            float4 k0 = kr[0], k1 = kr[1], k2 = kr[2], k3 = kr[3];
            S1[0]  = fmaf(q, k0.x, S1[0]);  S1[1]  = fmaf(q, k0.y, S1[1]);
            S1[2]  = fmaf(q, k0.z, S1[2]);  S1[3]  = fmaf(q, k0.w, S1[3]);
            S1[4]  = fmaf(q, k1.x, S1[4]);  S1[5]  = fmaf(q, k1.y, S1[5]);
            S1[6]  = fmaf(q, k1.z, S1[6]);  S1[7]  = fmaf(q, k1.w, S1[7]);
            S1[8]  = fmaf(q, k2.x, S1[8]);  S1[9]  = fmaf(q, k2.y, S1[9]);
            S1[10] = fmaf(q, k2.z, S1[10]); S1[11] = fmaf(q, k2.w, S1[11]);
            S1[12] = fmaf(q, k3.x, S1[12]); S1[13] = fmaf(q, k3.y, S1[13]);
            S1[14] = fmaf(q, k3.z, S1[14]); S1[15] = fmaf(q, k3.w, S1[15]);
        }
    }

    // ---------------- A1: grouped compute -> syncwarp -> write (in place) ----------------
#pragma unroll 1
    for (int sb = 0; sb < 49; sb += 7) {
        float a[7];
#pragma unroll
        for (int u = 0; u < 7; u++) {
            const float4* vr = reinterpret_cast<const float4*>(&myrow[(sb + u) * 16]);
            float4 v0 = vr[0], v1 = vr[1], v2 = vr[2], v3 = vr[3];
            float a0 = 0.f, a1 = 0.f;
            a0 = fmaf(S1[0],  v0.x, a0); a1 = fmaf(S1[1],  v0.y, a1);
            a0 = fmaf(S1[2],  v0.z, a0); a1 = fmaf(S1[3],  v0.w, a1);
            a0 = fmaf(S1[4],  v1.x, a0); a1 = fmaf(S1[5],  v1.y, a1);
            a0 = fmaf(S1[6],  v1.z, a0); a1 = fmaf(S1[7],  v1.w, a1);
            a0 = fmaf(S1[8],  v2.x, a0); a1 = fmaf(S1[9],  v2.y, a1);
            a0 = fmaf(S1[10], v2.z, a0); a1 = fmaf(S1[11], v2.w, a1);
            a0 = fmaf(S1[12], v3.x, a0); a1 = fmaf(S1[13], v3.y, a1);
            a0 = fmaf(S1[14], v3.z, a0); a1 = fmaf(S1[15], v3.w, a1);
            a[u] = a0 + a1;
        }
        __syncwarp();
#pragma unroll
        for (int u = 0; u < 7; u++) myrow[(sb + u) * 16 + t] = a[u];
        __syncwarp();
    }

    // ---------------- softmax1: quadrant-rotated access ----------------
    {
        const int r = (t >> 1) & 3;
#pragma unroll 1
        for (int s = t; s < 49; s += 16) {
            float4* row = reinterpret_cast<float4*>(&myrow[s * 16]);
            const int i0 = r, i1 = (r + 1) & 3, i2 = (r + 2) & 3, i3 = (r + 3) & 3;
            float4 v0 = row[i0], v1 = row[i1], v2 = row[i2], v3 = row[i3];
            float m = fmaxf(fmaxf(fmaxf(v0.x, v0.y), fmaxf(v0.z, v0.w)),
                            fmaxf(fmaxf(v1.x, v1.y), fmaxf(v1.z, v1.w)));
            m = fmaxf(m, fmaxf(fmaxf(fmaxf(v2.x, v2.y), fmaxf(v2.z, v2.w)),
                               fmaxf(fmaxf(v3.x, v3.y), fmaxf(v3.z, v3.w))));
            v0.x = __expf(v0.x - m); v0.y = __expf(v0.y - m); v0.z = __expf(v0.z - m); v0.w = __expf(v0.w - m);
            v1.x = __expf(v1.x - m); v1.y = __expf(v1.y - m); v1.z = __expf(v1.z - m); v1.w = __expf(v1.w - m);
            v2.x = __expf(v2.x - m); v2.y = __expf(v2.y - m); v2.z = __expf(v2.z - m); v2.w = __expf(v2.w - m);
            v3.x = __expf(v3.x - m); v3.y = __expf(v3.y - m); v3.z = __expf(v3.z - m); v3.w = __expf(v3.w - m);
            float sum = (v0.x + v0.y + v0.z + v0.w) + (v1.x + v1.y + v1.z + v1.w)
                      + (v2.x + v2.y + v2.z + v2.w) + (v3.x + v3.y + v3.z + v3.w);
            float inv = 1.f / sum;
            v0.x *= inv; v0.y *= inv; v0.z *= inv; v0.w *= inv;
            v1.x *= inv; v1.y *= inv; v1.z *= inv; v1.w *= inv;
            v2.x *= inv; v2.y *= inv; v2.z *= inv; v2.w *= inv;
            v3.x *= inv; v3.y *= inv; v3.z *= inv; v3.w *= inv;
            row[i0] = v0; row[i1] = v1; row[i2] = v2; row[i3] = v3;
        }
    }

    // ---------------- layer 2: chunks of 8 patches ----------------
    float S2[8];
#pragma unroll
    for (int e = 0; e < 8; e++) S2[e] = 0.f;
    const int d8 = t & 7;
    const int jp = t >> 3;

#pragma unroll 1
    for (int c0 = 0; c0 < 49; c0 += 8) {
        const int np = min(8, 49 - c0);
        __syncthreads();
        float vacc[4];
        const int s   = c0 + wrp;
        const int rV  = lane & 7;
        const int qtr = lane >> 3;          // V-pass sample quarter
        if (wrp < np) {
            // pass A: 16 rows (8Q+8K) x parity-split sample halves -> full 32 lanes
            {
                const int row16 = lane & 15;
                const int parA  = lane >> 4;
                const bool isQ  = (row16 < 8);
                const int r = row16 & 7;
                const float4* W4 = reinterpret_cast<const float4*>(
                    (isQ ? WQ2 : WK2) + s * 128 + r * 16);
                float4 w0 = W4[0], w1 = W4[1], w2 = W4[2], w3 = W4[3];
                const float scl = isQ ? INV7 : 1.f;
                const int dst = (isQ ? SM_QB : KB2) + wrp * 8 + r;
#pragma unroll 2
                for (int ii = 0; ii < 8; ii++) {
                    const int i = 2 * ii + parA;
                    const float4* tk = reinterpret_cast<const float4*>(&sh[SM_PB + i * 784 + s * 16]);
                    float acc = dot4(w3, tk[3], dot4(w2, tk[2], dot4(w1, tk[1], dot4(w0, tk[0], 0.f))));
                    sh[dst + i * 80] = acc * scl;
                }
            }
            // pass B: V rows x interleaved sample quarters (deferred)
            {
                const float4* W4 = reinterpret_cast<const float4*>(WV2 + s * 128 + rV * 16);
                float4 w0 = W4[0], w1 = W4[1], w2 = W4[2], w3 = W4[3];
#pragma unroll
                for (int ii = 0; ii < 4; ii++) {
                    const int i = 4 * ii + qtr;
                    const float4* tk = reinterpret_cast<const float4*>(&sh[SM_PB + i * 784 + s * 16]);
                    vacc[ii] = dot4(w3, tk[3], dot4(w2, tk[2], dot4(w1, tk[1], dot4(w0, tk[0], 0.f))));
                }
            }
        }
        __syncwarp();   // all tok2 reads complete before V2 overwrites
        if (wrp < np) {
#pragma unroll
            for (int ii = 0; ii < 4; ii++)
                sh[SM_PB + (4 * ii + qtr) * 784 + s * 16 + rV] = vacc[ii];
        }
        __syncthreads();
        // ---- G-phase: j split by t-parity (t<8 even j, t>=8 odd j) ----
#pragma unroll
        for (int jj = 0; jj < 4; jj++) {
            const int j = 2 * jj + jp;
            if (j < np) {
                float q2 = sh[SM_QB + ls * 80 + j * 8 + d8];
                const float4* kr = reinterpret_cast<const float4*>(&sh[KB2 + ls * 80 + j * 8]);
                float4 k0 = kr[0], k1 = kr[1];
                S2[0] = fmaf(q2, k0.x, S2[0]); S2[1] = fmaf(q2, k0.y, S2[1]);
                S2[2] = fmaf(q2, k0.z, S2[2]); S2[3] = fmaf(q2, k0.w, S2[3]);
                S2[4] = fmaf(q2, k1.x, S2[4]); S2[5] = fmaf(q2, k1.y, S2[5]);
                S2[6] = fmaf(q2, k1.z, S2[6]); S2[7] = fmaf(q2, k1.w, S2[7]);
            }
        }
    }
    // combine gram partials across j-parity halves (same sample)
#pragma unroll
    for (int e = 0; e < 8; e++) S2[e] += __shfl_xor_sync(0xffffffffu, S2[e], 8);

    // ---------------- A2: row-parity split across lane halves (25 iters) ----------------
#pragma unroll 1
    for (int ub = 0; ub < 25; ub += 7) {
        float a[7];
#pragma unroll
        for (int u2 = 0; u2 < 7; u2++) {
            const int u = ub + u2;
            const int srow = 2 * u + jp;
            float acc = 0.f;
            if (u < 25 && srow < 49) {
                const float4* vr = reinterpret_cast<const float4*>(&myrow[srow * 16]);
                float4 v0 = vr[0], v1 = vr[1];
                acc = fmaf(S2[0], v0.x, acc); acc = fmaf(S2[1], v0.y, acc);
                acc = fmaf(S2[2], v0.z, acc); acc = fmaf(S2[3], v0.w, acc);
                acc = fmaf(S2[4], v1.x, acc); acc = fmaf(S2[5], v1.y, acc);
                acc = fmaf(S2[6], v1.z, acc); acc = fmaf(S2[7], v1.w, acc);
            }
            a[u2] = acc;
        }
        __syncwarp();
#pragma unroll
        for (int u2 = 0; u2 < 7; u2++) {
            const int u = ub + u2;
            const int srow = 2 * u + jp;
            if (u < 25 && srow < 49) myrow[srow * 16 + d8] = a[u2];
        }
        __syncwarp();
    }

    // ---------------- softmax2: rotated access ----------------
    {
        const int r2 = (t >> 1) & 1;
#pragma unroll 1
        for (int s = t; s < 49; s += 16) {
            float4* row = reinterpret_cast<float4*>(&myrow[s * 16]);
            const int i0 = r2, i1 = r2 ^ 1;
            float4 v0 = row[i0], v1 = row[i1];
            float m = fmaxf(fmaxf(fmaxf(v0.x, v0.y), fmaxf(v0.z, v0.w)),
                            fmaxf(fmaxf(v1.x, v1.y), fmaxf(v1.z, v1.w)));
            v0.x = __expf(v0.x - m); v0.y = __expf(v0.y - m); v0.z = __expf(v0.z - m); v0.w = __expf(v0.w - m);
            v1.x = __expf(v1.x - m); v1.y = __expf(v1.y - m); v1.z = __expf(v1.z - m); v1.w = __expf(v1.w - m);
            float sum = (v0.x + v0.y + v0.z + v0.w) + (v1.x + v1.y + v1.z + v1.w);
            float inv = 1.f / sum;
            v0.x *= inv; v0.y *= inv; v0.z *= inv; v0.w *= inv;
            v1.x *= inv; v1.y *= inv; v1.z *= inv; v1.w *= inv;
            row[i0] = v0; row[i1] = v1;
        }
    }

    // ---------------- FC head: fc1w staged in two K-halves, stride 204 ----------------
    float acc = sh[SM_F1B + t];
    __syncthreads();
    for (int idx = tid; idx < 768; idx += NTHR) {    // 16 rows x 48 float4 (cols 0..191)
        int j = idx / 48, c4 = idx - j * 48;
        *reinterpret_cast<float4*>(&sh[SM_QB + j * 204 + c4 * 4]) =
            *reinterpret_cast<const float4*>(&fc1w[j * 392 + c4 * 4]);
    }
    __syncthreads();
#pragma unroll 1
    for (int s = 0; s < 24; s++) {
        float4 a0 = *reinterpret_cast<const float4*>(&myrow[s * 16]);
        float4 a1 = *reinterpret_cast<const float4*>(&myrow[s * 16 + 4]);
        float4 w0 = *reinterpret_cast<const float4*>(&sh[SM_QB + t * 204 + s * 8]);
        float4 w1 = *reinterpret_cast<const float4*>(&sh[SM_QB + t * 204 + s * 8 + 4]);
        acc = dot4(w0, a0, acc);
        acc = dot4(w1, a1, acc);
    }
    __syncthreads();
    for (int idx = tid; idx < 800; idx += NTHR) {    // 16 rows x 50 float4 (cols 192..391)
        int j = idx / 50, c4 = idx - j * 50;
        *reinterpret_cast<float4*>(&sh[SM_QB + j * 204 + c4 * 4]) =
            *reinterpret_cast<const float4*>(&fc1w[j * 392 + 192 + c4 * 4]);
    }
    __syncthreads();
#pragma unroll 1
    for (int s = 24; s < 49; s++) {
        float4 a0 = *reinterpret_cast<const float4*>(&myrow[s * 16]);
        float4 a1 = *reinterpret_cast<const float4*>(&myrow[s * 16 + 4]);
        float4 w0 = *reinterpret_cast<const float4*>(&sh[SM_QB + t * 204 + (s - 24) * 8]);
        float4 w1 = *reinterpret_cast<const float4*>(&sh[SM_QB + t * 204 + (s - 24) * 8 + 4]);
        acc = dot4(w0, a0, acc);
        acc = dot4(w1, a1, acc);
    }
    sh[SM_H + ls * 16 + t] = fmaxf(acc, 0.f);
    __syncwarp();

    {
        float lg = 0.f;
        if (t < 10) {
            const float4* w  = reinterpret_cast<const float4*>(&sh[SM_F2W + t * 16]);
            const float4* hh = reinterpret_cast<const float4*>(&sh[SM_H + ls * 16]);
            lg = dot4(w[0], hh[0], lg); lg = dot4(w[1], hh[1], lg);
            lg = dot4(w[2], hh[2], lg); lg = dot4(w[3], hh[3], lg);
            lg += sh[SM_F2B + t];
        }
        sh[SM_LG + ls * 16 + t] = lg;
    }
    __syncwarp();

    if (t == 0 && b < B) {
        const float* lrow = &sh[SM_LG + ls * 16];
        float m = lrow[0];
#pragma unroll
        for (int c = 1; c < 10; c++) m = fmaxf(m, lrow[c]);
        float ex[10], sum = 0.f;
#pragma unroll
        for (int c = 0; c < 10; c++) { ex[c] = __expf(lrow[c] - m); sum += ex[c]; }
        float inv = 1.f / sum;
        float* o = out + (size_t)b * 10;
#pragma unroll
        for (int c = 0; c < 10; c++) o[c] = ex[c] * inv;
    }
}

extern "C" void kernel_launch(void* const* d_in, const int* in_sizes, int n_in,
                              void* d_out, int out_size) {
    const float* x   = (const float*)d_in[0];
    const float* pe  = (const float*)d_in[1];
    const float* WQ1 = (const float*)d_in[2];
    const float* WK1 = (const float*)d_in[3];
    const float* WV1 = (const float*)d_in[4];
    const float* WQ2 = (const float*)d_in[5];
    const float* WK2 = (const float*)d_in[6];
    const float* WV2 = (const float*)d_in[7];
    const float* f1w = (const float*)d_in[8];
    const float* f1b = (const float*)d_in[9];
    const float* f2w = (const float*)d_in[10];
    const float* f2b = (const float*)d_in[11];
    float* out = (float*)d_out;

    int B = in_sizes[0] / (3 * 28 * 28);
    int grid = (B + GRP - 1) / GRP;
    size_t smem = (size_t)SM_TOT * sizeof(float);

    cudaFuncSetAttribute(vit_fused_kernel,
                         cudaFuncAttributeMaxDynamicSharedMemorySize, (int)smem);
    vit_fused_kernel<<<grid, NTHR, smem>>>(x, pe, WQ1, WK1, WV1, WQ2, WK2, WV2,
                                           f1w, f1b, f2w, f2b, out, B);
}